// round 1
// baseline (speedup 1.0000x reference)
#include <cuda_runtime.h>
#include <math.h>

#define B_   8
#define S_   4096
#define H_   1024
#define R_   (B_ * H_)
#define CAP  128
#define TAU  3.3f

// ---------------- device scratch (static: no allocation allowed) ----------------
__device__ float2 g_buf[R_ * CAP];   // survivor (score, value) per row, 8 MB
__device__ int    g_cnt[R_];
__device__ float  g_pooled[R_];
__device__ int    g_fail[R_];
__device__ int    g_nfail;

__device__ __forceinline__ float neg_inf() { return __int_as_float(0xff800000); }

// ---------------- 0: zero counters ----------------
__global__ void k_init() {
    int i = blockIdx.x * blockDim.x + threadIdx.x;
    if (i < R_) g_cnt[i] = 0;
    if (i == 0) g_nfail = 0;
}

// ---------------- 1: streaming filter ----------------
// warp = 32 consecutive h (coalesced hidden), per-lane float4 gumbel stream.
// survivor condition: log(relu(x)) + g > TAU  (x<=0 -> NaN/-inf -> false)
__device__ __forceinline__ void flt_test(float x, float g, int r) {
    float sc = __logf(x) + g;          // lg2-based; NaN for x<0, -inf for x==0
    if (sc > TAU) {
        int p = atomicAdd(&g_cnt[r], 1);
        if (p < CAP) g_buf[r * CAP + p] = make_float2(sc, x);
    }
}

__global__ __launch_bounds__(256) void k_filter(const float* __restrict__ hidden,
                                                const float* __restrict__ gumbel) {
    int w    = (blockIdx.x * blockDim.x + threadIdx.x) >> 5;  // global warp id [0,4096)
    int lane = threadIdx.x & 31;
    int sc_i = w & 15;          // s-chunk  [0,16)
    int hw   = (w >> 4) & 31;   // h-warp   [0,32)
    int b    = w >> 9;          // batch    [0,8)
    int h    = hw * 32 + lane;
    int r    = b * H_ + h;
    int s0   = sc_i * 256;

    const float*  hp = hidden + ((size_t)b * S_ + s0) * H_ + h;
    const float4* gp = (const float4*)(gumbel + (size_t)r * S_ + s0);

#pragma unroll 2
    for (int i = 0; i < 64; ++i) {
        float4 g4 = gp[i];
        float x0 = hp[(size_t)(4 * i + 0) * H_];
        float x1 = hp[(size_t)(4 * i + 1) * H_];
        float x2 = hp[(size_t)(4 * i + 2) * H_];
        float x3 = hp[(size_t)(4 * i + 3) * H_];
        flt_test(x0, g4.x, r);
        flt_test(x1, g4.y, r);
        flt_test(x2, g4.z, r);
        flt_test(x3, g4.w, r);
    }
}

// ---------------- 2: per-row top-8 over survivors ----------------
// one warp per row; lane holds up to 4 candidates in named registers; 8 rounds
// of warp-argmax. Rows with cnt<8 or cnt>CAP are deferred to the fallback.
__global__ __launch_bounds__(256) void k_select() {
    int row  = (blockIdx.x * blockDim.x + threadIdx.x) >> 5;
    int lane = threadIdx.x & 31;
    if (row >= R_) return;

    int cnt = g_cnt[row];
    if (cnt < 8 || cnt > CAP) {
        if (lane == 0) {
            int p = atomicAdd(&g_nfail, 1);
            g_fail[p] = row;
        }
        return;
    }

    const float NI = neg_inf();
    float sc0 = NI, sc1 = NI, sc2 = NI, sc3 = NI;
    float v0 = 0.f, v1 = 0.f, v2 = 0.f, v3 = 0.f;
    int base = row * CAP;
    if (lane      < cnt) { float2 c = g_buf[base + lane];      sc0 = c.x; v0 = c.y; }
    if (lane + 32 < cnt) { float2 c = g_buf[base + lane + 32]; sc1 = c.x; v1 = c.y; }
    if (lane + 64 < cnt) { float2 c = g_buf[base + lane + 64]; sc2 = c.x; v2 = c.y; }
    if (lane + 96 < cnt) { float2 c = g_buf[base + lane + 96]; sc3 = c.x; v3 = c.y; }

    float sum = 0.f;
    for (int round = 0; round < 8; ++round) {
        float bs = sc0, bv = v0; int bi = 0;
        if (sc1 > bs) { bs = sc1; bv = v1; bi = 1; }
        if (sc2 > bs) { bs = sc2; bv = v2; bi = 2; }
        if (sc3 > bs) { bs = sc3; bv = v3; bi = 3; }
        float m = bs;
#pragma unroll
        for (int off = 16; off > 0; off >>= 1)
            m = fmaxf(m, __shfl_xor_sync(0xffffffffu, m, off));
        unsigned ball = __ballot_sync(0xffffffffu, bs == m);
        int src = __ffs(ball) - 1;
        sum += __shfl_sync(0xffffffffu, bv, src);
        if (lane == src) {
            if      (bi == 0) sc0 = neg_inf();
            else if (bi == 1) sc1 = neg_inf();
            else if (bi == 2) sc2 = neg_inf();
            else              sc3 = neg_inf();
        }
    }
    if (lane == 0) g_pooled[row] = sum;
}

// ---------------- 3: exact fallback for failed rows (expected: none) ----------------
__global__ __launch_bounds__(256) void k_fallback(const float* __restrict__ hidden,
                                                  const float* __restrict__ gumbel) {
    __shared__ float fsc[2048];
    __shared__ float fval[2048];
    __shared__ float rsc[256];
    __shared__ int   rid[256];

    int nf  = g_nfail;
    int tid = threadIdx.x;
    const float NI = neg_inf();

    for (int fi = blockIdx.x; fi < nf; fi += gridDim.x) {
        int r = g_fail[fi];
        int b = r >> 10;
        int h = r & (H_ - 1);

        // per-thread top-8 over its strided s values (16 each)
        float lsc[8], lval[8];
#pragma unroll
        for (int j = 0; j < 8; ++j) { lsc[j] = NI; lval[j] = 0.f; }

        for (int s = tid; s < S_; s += 256) {
            float x = hidden[((size_t)b * S_ + s) * H_ + h];
            float g = gumbel[(size_t)r * S_ + s];
            float sc = (x > 0.f) ? (__logf(x) + g) : NI;
            if (sc > lsc[7]) {
                lsc[7] = sc; lval[7] = x;
#pragma unroll
                for (int j = 7; j > 0; --j) {
                    if (lsc[j] > lsc[j - 1]) {
                        float ts = lsc[j]; lsc[j] = lsc[j - 1]; lsc[j - 1] = ts;
                        float tv = lval[j]; lval[j] = lval[j - 1]; lval[j - 1] = tv;
                    }
                }
            }
        }
#pragma unroll
        for (int j = 0; j < 8; ++j) {
            fsc [tid * 8 + j] = lsc[j];
            fval[tid * 8 + j] = lval[j];
        }
        __syncthreads();

        float sum = 0.f;
        for (int round = 0; round < 8; ++round) {
            // local argmax over 8 strided candidates
            float bs = NI; int bi = tid;
#pragma unroll
            for (int k = 0; k < 8; ++k) {
                int idx = tid + 256 * k;
                if (fsc[idx] > bs) { bs = fsc[idx]; bi = idx; }
            }
            rsc[tid] = bs; rid[tid] = bi;
            __syncthreads();
            for (int off = 128; off > 0; off >>= 1) {
                if (tid < off && rsc[tid + off] > rsc[tid]) {
                    rsc[tid] = rsc[tid + off];
                    rid[tid] = rid[tid + off];
                }
                __syncthreads();
            }
            int win = rid[0];
            sum += fval[win];          // 0 for -inf entries: matches reference
            __syncthreads();
            if (tid == 0) fsc[win] = NI;
            __syncthreads();
        }
        if (tid == 0) g_pooled[r] = sum;
        __syncthreads();
    }
}

// ---------------- 4: out = tanh(pooled @ W^T + bias) ----------------
__global__ __launch_bounds__(256) void k_gemm(const float* __restrict__ W,
                                              const float* __restrict__ bias,
                                              float* __restrict__ out) {
    int j = blockIdx.x;            // output feature
    float acc[8];
#pragma unroll
    for (int bb = 0; bb < 8; ++bb) acc[bb] = 0.f;

    for (int h = threadIdx.x; h < H_; h += 256) {
        float wv = W[(size_t)j * H_ + h];
#pragma unroll
        for (int bb = 0; bb < 8; ++bb)
            acc[bb] += g_pooled[bb * H_ + h] * wv;
    }
#pragma unroll
    for (int bb = 0; bb < 8; ++bb)
#pragma unroll
        for (int off = 16; off > 0; off >>= 1)
            acc[bb] += __shfl_xor_sync(0xffffffffu, acc[bb], off);

    __shared__ float tot[8];
    if (threadIdx.x < 8) tot[threadIdx.x] = 0.f;
    __syncthreads();
    if ((threadIdx.x & 31) == 0) {
#pragma unroll
        for (int bb = 0; bb < 8; ++bb) atomicAdd(&tot[bb], acc[bb]);
    }
    __syncthreads();
    if (threadIdx.x < 8)
        out[threadIdx.x * H_ + j] = tanhf(tot[threadIdx.x] + bias[j]);
}

// ---------------- launch ----------------
extern "C" void kernel_launch(void* const* d_in, const int* in_sizes, int n_in,
                              void* d_out, int out_size) {
    const float* hidden = (const float*)d_in[0];
    const float* gumbel = (const float*)d_in[1];
    const float* W      = (const float*)d_in[2];
    const float* bias   = (const float*)d_in[3];
    float*       out    = (float*)d_out;
    (void)in_sizes; (void)n_in; (void)out_size;

    k_init    <<<32,   256>>>();
    k_filter  <<<512,  256>>>(hidden, gumbel);
    k_select  <<<1024, 256>>>();
    k_fallback<<<64,   256>>>(hidden, gumbel);
    k_gemm    <<<1024, 256>>>(W, bias, out);
}

// round 2
// speedup vs baseline: 1.0846x; 1.0846x over previous
#include <cuda_runtime.h>
#include <math.h>

#define B_   8
#define S_   4096
#define H_   1024
#define R_   (B_ * H_)
#define CAP  128
#define TAU  3.3f

// ---------------- device scratch (static: no allocation allowed) ----------------
__device__ float2 g_buf[R_ * CAP];   // survivor (score, value) per row, 8 MB
__device__ int    g_cnt[R_];
__device__ float  g_pooled[R_];
__device__ int    g_fail[R_];
__device__ int    g_nfail;

__device__ __forceinline__ float neg_inf() { return __int_as_float(0xff800000); }

// ---------------- 0: zero counters ----------------
__global__ void k_init() {
    int i = blockIdx.x * blockDim.x + threadIdx.x;
    if (i < R_) g_cnt[i] = 0;
    if (i == 0) g_nfail = 0;
}

// ---------------- 1: streaming filter (smem-transposed gumbel) ----------------
// Block tile: 32 h x 256 s. Phase 1: gumbel loaded coalesced (lanes along s)
// into smem with XOR swizzle bank=(h+s)&31 (conflict-free store AND load).
// Phase 2: hidden read coalesced (lanes along h), gumbel from smem.
// Survivor condition: log(relu(x)) + g > TAU  (x<=0 -> NaN/-inf -> false).
__global__ __launch_bounds__(256) void k_filter(const float* __restrict__ hidden,
                                                const float* __restrict__ gumbel) {
    __shared__ float sg[256 * 32];   // 32 KB

    int blk  = blockIdx.x;           // 0..4095
    int sblk = blk & 15;             // 16 s-blocks
    int hblk = (blk >> 4) & 31;      // 32 h-blocks
    int b    = blk >> 9;             // 8 batches
    int s0   = sblk * 256;
    int h0   = hblk * 32;
    int w    = threadIdx.x >> 5;
    int lane = threadIdx.x & 31;

    // phase 1: load 32 rows x 256 s of gumbel, coalesced, store swizzled
    const float* gbase = gumbel + ((size_t)(b * H_ + h0)) * S_ + s0;
#pragma unroll
    for (int q = 0; q < 4; ++q) {
        int hl = w * 4 + q;
        const float* gr = gbase + (size_t)hl * S_;
#pragma unroll
        for (int it = 0; it < 8; ++it) {
            int s = it * 32 + lane;
            sg[s * 32 + ((hl + s) & 31)] = gr[s];
        }
    }
    __syncthreads();

    // phase 2: warp w covers s in [w*32, w*32+32), lane = h offset
    const float* hbase = hidden + ((size_t)b * S_ + s0) * H_ + h0 + lane;
    int r = b * H_ + h0 + lane;

#pragma unroll 4
    for (int i = 0; i < 32; ++i) {
        int s = w * 32 + i;
        float x = hbase[(size_t)s * H_];
        float g = sg[s * 32 + ((lane + s) & 31)];
        float sc = __logf(x) + g;    // NaN for x<0, -inf for x==0: never > TAU
        if (sc > TAU) {
            int p = atomicAdd(&g_cnt[r], 1);
            if (p < CAP) g_buf[r * CAP + p] = make_float2(sc, x);
        }
    }
}

// ---------------- 2: per-row top-8 over survivors ----------------
__global__ __launch_bounds__(256) void k_select() {
    int row  = (blockIdx.x * blockDim.x + threadIdx.x) >> 5;
    int lane = threadIdx.x & 31;
    if (row >= R_) return;

    int cnt = g_cnt[row];
    if (cnt < 8 || cnt > CAP) {
        if (lane == 0) {
            int p = atomicAdd(&g_nfail, 1);
            g_fail[p] = row;
        }
        return;
    }

    const float NI = neg_inf();
    float sc0 = NI, sc1 = NI, sc2 = NI, sc3 = NI;
    float v0 = 0.f, v1 = 0.f, v2 = 0.f, v3 = 0.f;
    int base = row * CAP;
    if (lane      < cnt) { float2 c = g_buf[base + lane];      sc0 = c.x; v0 = c.y; }
    if (lane + 32 < cnt) { float2 c = g_buf[base + lane + 32]; sc1 = c.x; v1 = c.y; }
    if (lane + 64 < cnt) { float2 c = g_buf[base + lane + 64]; sc2 = c.x; v2 = c.y; }
    if (lane + 96 < cnt) { float2 c = g_buf[base + lane + 96]; sc3 = c.x; v3 = c.y; }

    float sum = 0.f;
    for (int round = 0; round < 8; ++round) {
        float bs = sc0, bv = v0; int bi = 0;
        if (sc1 > bs) { bs = sc1; bv = v1; bi = 1; }
        if (sc2 > bs) { bs = sc2; bv = v2; bi = 2; }
        if (sc3 > bs) { bs = sc3; bv = v3; bi = 3; }
        float m = bs;
#pragma unroll
        for (int off = 16; off > 0; off >>= 1)
            m = fmaxf(m, __shfl_xor_sync(0xffffffffu, m, off));
        unsigned ball = __ballot_sync(0xffffffffu, bs == m);
        int src = __ffs(ball) - 1;
        sum += __shfl_sync(0xffffffffu, bv, src);
        if (lane == src) {
            if      (bi == 0) sc0 = neg_inf();
            else if (bi == 1) sc1 = neg_inf();
            else if (bi == 2) sc2 = neg_inf();
            else              sc3 = neg_inf();
        }
    }
    if (lane == 0) g_pooled[row] = sum;
}

// ---------------- 3: exact fallback for failed rows (expected: none) ----------------
__global__ __launch_bounds__(256) void k_fallback(const float* __restrict__ hidden,
                                                  const float* __restrict__ gumbel) {
    __shared__ float fsc[2048];
    __shared__ float fval[2048];
    __shared__ float rsc[256];
    __shared__ int   rid[256];

    int nf  = g_nfail;
    int tid = threadIdx.x;
    const float NI = neg_inf();

    for (int fi = blockIdx.x; fi < nf; fi += gridDim.x) {
        int r = g_fail[fi];
        int b = r >> 10;
        int h = r & (H_ - 1);

        float lsc[8], lval[8];
#pragma unroll
        for (int j = 0; j < 8; ++j) { lsc[j] = NI; lval[j] = 0.f; }

        for (int s = tid; s < S_; s += 256) {
            float x = hidden[((size_t)b * S_ + s) * H_ + h];
            float g = gumbel[(size_t)r * S_ + s];
            float sc = (x > 0.f) ? (__logf(x) + g) : NI;
            if (sc > lsc[7]) {
                lsc[7] = sc; lval[7] = x;
#pragma unroll
                for (int j = 7; j > 0; --j) {
                    if (lsc[j] > lsc[j - 1]) {
                        float ts = lsc[j]; lsc[j] = lsc[j - 1]; lsc[j - 1] = ts;
                        float tv = lval[j]; lval[j] = lval[j - 1]; lval[j - 1] = tv;
                    }
                }
            }
        }
#pragma unroll
        for (int j = 0; j < 8; ++j) {
            fsc [tid * 8 + j] = lsc[j];
            fval[tid * 8 + j] = lval[j];
        }
        __syncthreads();

        float sum = 0.f;
        for (int round = 0; round < 8; ++round) {
            float bs = NI; int bi = tid;
#pragma unroll
            for (int k = 0; k < 8; ++k) {
                int idx = tid + 256 * k;
                if (fsc[idx] > bs) { bs = fsc[idx]; bi = idx; }
            }
            rsc[tid] = bs; rid[tid] = bi;
            __syncthreads();
            for (int off = 128; off > 0; off >>= 1) {
                if (tid < off && rsc[tid + off] > rsc[tid]) {
                    rsc[tid] = rsc[tid + off];
                    rid[tid] = rid[tid + off];
                }
                __syncthreads();
            }
            int win = rid[0];
            sum += fval[win];
            __syncthreads();
            if (tid == 0) fsc[win] = NI;
            __syncthreads();
        }
        if (tid == 0) g_pooled[r] = sum;
        __syncthreads();
    }
}

// ---------------- 4: out = tanh(pooled @ W^T + bias) ----------------
__global__ __launch_bounds__(256) void k_gemm(const float* __restrict__ W,
                                              const float* __restrict__ bias,
                                              float* __restrict__ out) {
    int j = blockIdx.x;
    float acc[8];
#pragma unroll
    for (int bb = 0; bb < 8; ++bb) acc[bb] = 0.f;

    for (int h = threadIdx.x; h < H_; h += 256) {
        float wv = W[(size_t)j * H_ + h];
#pragma unroll
        for (int bb = 0; bb < 8; ++bb)
            acc[bb] += g_pooled[bb * H_ + h] * wv;
    }
#pragma unroll
    for (int bb = 0; bb < 8; ++bb)
#pragma unroll
        for (int off = 16; off > 0; off >>= 1)
            acc[bb] += __shfl_xor_sync(0xffffffffu, acc[bb], off);

    __shared__ float tot[8];
    if (threadIdx.x < 8) tot[threadIdx.x] = 0.f;
    __syncthreads();
    if ((threadIdx.x & 31) == 0) {
#pragma unroll
        for (int bb = 0; bb < 8; ++bb) atomicAdd(&tot[bb], acc[bb]);
    }
    __syncthreads();
    if (threadIdx.x < 8)
        out[threadIdx.x * H_ + j] = tanhf(tot[threadIdx.x] + bias[j]);
}

// ---------------- launch ----------------
extern "C" void kernel_launch(void* const* d_in, const int* in_sizes, int n_in,
                              void* d_out, int out_size) {
    const float* hidden = (const float*)d_in[0];
    const float* gumbel = (const float*)d_in[1];
    const float* W      = (const float*)d_in[2];
    const float* bias   = (const float*)d_in[3];
    float*       out    = (float*)d_out;
    (void)in_sizes; (void)n_in; (void)out_size;

    k_init    <<<32,   256>>>();
    k_filter  <<<4096, 256>>>(hidden, gumbel);
    k_select  <<<1024, 256>>>();
    k_fallback<<<64,   256>>>(hidden, gumbel);
    k_gemm    <<<1024, 256>>>(W, bias, out);
}

// round 3
// speedup vs baseline: 1.1586x; 1.0682x over previous
#include <cuda_runtime.h>
#include <math.h>

#define B_   8
#define S_   4096
#define H_   1024
#define R_   (B_ * H_)
#define CAP  128
// threshold in lg2 domain: ln(x)+g > 3.3  <=>  lg2(x) + g/ln2 > 3.3/ln2
#define TAU_LG2   4.76107544f
#define INV_LN2   1.44269504f

// ---------------- device scratch (zero-initialized at load; select restores) ----------------
__device__ float2 g_buf[R_ * CAP];   // survivor (score, value) per row
__device__ int    g_cnt[R_];         // zeroed at init; k_select resets after use
__device__ float  g_pooled[R_];

__device__ __forceinline__ float neg_inf() { return __int_as_float(0xff800000); }

// ---------------- 1: streaming filter (smem-transposed gumbel, MLP-8 loads) ----------------
// Block tile: 32 h x 256 s. Phase 1: gumbel loaded coalesced (lanes along s)
// into smem with XOR swizzle bank=(h+s)&31. Phase 2: hidden coalesced (lanes
// along h), loads front-batched 8 at a time for MLP.
__global__ __launch_bounds__(256) void k_filter(const float* __restrict__ hidden,
                                                const float* __restrict__ gumbel) {
    __shared__ float sg[256 * 32];   // 32 KB

    int blk  = blockIdx.x;           // 0..4095
    int sblk = blk & 15;
    int hblk = (blk >> 4) & 31;
    int b    = blk >> 9;
    int s0   = sblk * 256;
    int h0   = hblk * 32;
    int w    = threadIdx.x >> 5;
    int lane = threadIdx.x & 31;

    // phase 1: 32 rows x 256 s of gumbel, coalesced, swizzled store
    const float* gbase = gumbel + ((size_t)(b * H_ + h0)) * S_ + s0;
#pragma unroll
    for (int q = 0; q < 4; ++q) {
        int hl = w * 4 + q;
        const float* gr = gbase + (size_t)hl * S_;
#pragma unroll
        for (int it = 0; it < 8; ++it) {
            int s = it * 32 + lane;
            sg[s * 32 + ((hl + s) & 31)] = gr[s];
        }
    }
    __syncthreads();

    // phase 2: warp w covers s in [w*32, (w+1)*32), lane = h offset
    const float* hbase = hidden + ((size_t)b * S_ + s0 + w * 32) * H_ + h0 + lane;
    int r = b * H_ + h0 + lane;

#pragma unroll
    for (int ii = 0; ii < 4; ++ii) {
        float xs[8], gs[8];
#pragma unroll
        for (int j = 0; j < 8; ++j)
            xs[j] = hbase[(size_t)(ii * 8 + j) * H_];
#pragma unroll
        for (int j = 0; j < 8; ++j) {
            int s = w * 32 + ii * 8 + j;
            gs[j] = sg[s * 32 + ((lane + s) & 31)];
        }
#pragma unroll
        for (int j = 0; j < 8; ++j) {
            // sc = lg2(x) + g/ln2 ; NaN for x<0, -inf for x==0: never > TAU
            float sc = fmaf(gs[j], INV_LN2, __log2f(xs[j]));
            if (sc > TAU_LG2) {
                int p = atomicAdd(&g_cnt[r], 1);
                if (p < CAP) g_buf[r * CAP + p] = make_float2(sc, xs[j]);
            }
        }
    }
}

// ---------------- 2: per-row top-8 over survivors (+ inline exact fallback) ----------------
__global__ __launch_bounds__(256) void k_select(const float* __restrict__ hidden,
                                                const float* __restrict__ gumbel) {
    int row  = (blockIdx.x * blockDim.x + threadIdx.x) >> 5;
    int lane = threadIdx.x & 31;
    if (row >= R_) return;

    const float NI = neg_inf();
    int cnt = g_cnt[row];
    // restore counter for the next graph replay (deterministic state)
    if (lane == 0) g_cnt[row] = 0;

    float sum = 0.f;

    if (cnt >= 8 && cnt <= CAP) {
        // fast path: warp top-8 over <=128 survivors held in 4 register slots
        float sc0 = NI, sc1 = NI, sc2 = NI, sc3 = NI;
        float v0 = 0.f, v1 = 0.f, v2 = 0.f, v3 = 0.f;
        int base = row * CAP;
        if (lane      < cnt) { float2 c = g_buf[base + lane];      sc0 = c.x; v0 = c.y; }
        if (lane + 32 < cnt) { float2 c = g_buf[base + lane + 32]; sc1 = c.x; v1 = c.y; }
        if (lane + 64 < cnt) { float2 c = g_buf[base + lane + 64]; sc2 = c.x; v2 = c.y; }
        if (lane + 96 < cnt) { float2 c = g_buf[base + lane + 96]; sc3 = c.x; v3 = c.y; }

        for (int round = 0; round < 8; ++round) {
            float bs = sc0, bv = v0; int bi = 0;
            if (sc1 > bs) { bs = sc1; bv = v1; bi = 1; }
            if (sc2 > bs) { bs = sc2; bv = v2; bi = 2; }
            if (sc3 > bs) { bs = sc3; bv = v3; bi = 3; }
            float m = bs;
#pragma unroll
            for (int off = 16; off > 0; off >>= 1)
                m = fmaxf(m, __shfl_xor_sync(0xffffffffu, m, off));
            unsigned ball = __ballot_sync(0xffffffffu, bs == m);
            int src = __ffs(ball) - 1;
            sum += __shfl_sync(0xffffffffu, bv, src);
            if (lane == src) {
                if      (bi == 0) sc0 = NI;
                else if (bi == 1) sc1 = NI;
                else if (bi == 2) sc2 = NI;
                else              sc3 = NI;
            }
        }
    } else {
        // exact fallback (rare; expected never): warp rescans the full row
        int b = row >> 10;
        int h = row & (H_ - 1);
        const float* hp = hidden + (size_t)b * S_ * H_ + h;
        const float* gp = gumbel + (size_t)row * S_;

        float lsc[8], lv[8];
#pragma unroll
        for (int j = 0; j < 8; ++j) { lsc[j] = NI; lv[j] = 0.f; }

        for (int s = lane; s < S_; s += 32) {
            float x = hp[(size_t)s * H_];
            float g = gp[s];
            float sc = (x > 0.f) ? fmaf(g, INV_LN2, __log2f(x)) : NI;
            if (sc > lsc[7]) {
                lsc[7] = sc; lv[7] = x;
#pragma unroll
                for (int j = 7; j > 0; --j) {
                    if (lsc[j] > lsc[j - 1]) {
                        float ts = lsc[j]; lsc[j] = lsc[j - 1]; lsc[j - 1] = ts;
                        float tv = lv[j];  lv[j]  = lv[j - 1];  lv[j - 1]  = tv;
                    }
                }
            }
        }
        // merge: 8 rounds of warp argmax over per-lane sorted lists
        int ptr = 0;
        for (int round = 0; round < 8; ++round) {
            float cand = NI, cval = 0.f;
#pragma unroll
            for (int j = 0; j < 8; ++j)
                if (j == ptr) { cand = lsc[j]; cval = lv[j]; }
            float m = cand;
#pragma unroll
            for (int off = 16; off > 0; off >>= 1)
                m = fmaxf(m, __shfl_xor_sync(0xffffffffu, m, off));
            unsigned ball = __ballot_sync(0xffffffffu, (cand == m) && (ptr < 8));
            if (ball == 0u) {            // all remaining are -inf (e.g. zero row)
                // value contribution is 0 for empty slots: matches reference
                continue;
            }
            int src = __ffs(ball) - 1;
            sum += __shfl_sync(0xffffffffu, cval, src);
            if (lane == src) ptr++;
        }
    }

    if (lane == 0) g_pooled[row] = sum;
}

// ---------------- 3: out = tanh(pooled @ W^T + bias) ----------------
__global__ __launch_bounds__(256) void k_gemm(const float* __restrict__ W,
                                              const float* __restrict__ bias,
                                              float* __restrict__ out) {
    int j = blockIdx.x;
    float acc[8];
#pragma unroll
    for (int bb = 0; bb < 8; ++bb) acc[bb] = 0.f;

    for (int h = threadIdx.x; h < H_; h += 256) {
        float wv = W[(size_t)j * H_ + h];
#pragma unroll
        for (int bb = 0; bb < 8; ++bb)
            acc[bb] += g_pooled[bb * H_ + h] * wv;
    }
#pragma unroll
    for (int bb = 0; bb < 8; ++bb)
#pragma unroll
        for (int off = 16; off > 0; off >>= 1)
            acc[bb] += __shfl_xor_sync(0xffffffffu, acc[bb], off);

    __shared__ float tot[8];
    if (threadIdx.x < 8) tot[threadIdx.x] = 0.f;
    __syncthreads();
    if ((threadIdx.x & 31) == 0) {
#pragma unroll
        for (int bb = 0; bb < 8; ++bb) atomicAdd(&tot[bb], acc[bb]);
    }
    __syncthreads();
    if (threadIdx.x < 8)
        out[threadIdx.x * H_ + j] = tanhf(tot[threadIdx.x] + bias[j]);
}

// ---------------- launch ----------------
extern "C" void kernel_launch(void* const* d_in, const int* in_sizes, int n_in,
                              void* d_out, int out_size) {
    const float* hidden = (const float*)d_in[0];
    const float* gumbel = (const float*)d_in[1];
    const float* W      = (const float*)d_in[2];
    const float* bias   = (const float*)d_in[3];
    float*       out    = (float*)d_out;
    (void)in_sizes; (void)n_in; (void)out_size;

    k_filter<<<4096, 256>>>(hidden, gumbel);
    k_select<<<1024, 256>>>(hidden, gumbel);
    k_gemm  <<<1024, 256>>>(W, bias, out);
}